// round 1
// baseline (speedup 1.0000x reference)
#include <cuda_runtime.h>
#include <math.h>

#define B   8
#define C   64
#define DW  128
#define IH  256
#define IW  256
#define HW  65536
#define EPS 1e-6f

// ---------------- device scratch (static allocation is the sanctioned path) ----
__device__ float g_w1[B*DW*C];      // normalized w1 [b][o][c]
__device__ float g_w2[B*DW*9];      // normalized w2 [b][ch][9]
__device__ float g_w3[B*C*C];       // normalized w3 [b][o][c]
__device__ float g_w4[B*DW*C];      // normalized w4 [b][o][c]
__device__ float g_w5[B*C*C];       // normalized w5 [b][o][c]
__device__ float g_t1[(size_t)B*DW*HW];  // after LN1+pw1   (268 MB)
__device__ float g_t2[(size_t)B*C*HW];   // after dw+gate   (134 MB)
__device__ float g_pool[B*C];
__device__ float g_sca[B*C];

// ---------------- prep: frobenius-normalize all hyper weights, zero pool -------
__global__ void k_prep(const float* __restrict__ w1, const float* __restrict__ w2,
                       const float* __restrict__ w3, const float* __restrict__ w4,
                       const float* __restrict__ w5) {
    int blk = blockIdx.x, t = threadIdx.x;   // 32 threads per block
    const float* src; float* dst; int L;
    if (blk < 1024)      { int r = blk;        src = w1 + r*64; dst = g_w1 + r*64; L = 64; }
    else if (blk < 2048) { int r = blk - 1024; src = w2 + r*9;  dst = g_w2 + r*9;  L = 9;  }
    else if (blk < 2560) { int r = blk - 2048; src = w3 + r*64; dst = g_w3 + r*64; L = 64; }
    else if (blk < 3584) { int r = blk - 2560; src = w4 + r*64; dst = g_w4 + r*64; L = 64; }
    else if (blk < 4096) { int r = blk - 3584; src = w5 + r*64; dst = g_w5 + r*64; L = 64; }
    else {  // zero the pooling accumulator
        for (int i = t; i < B*C; i += 32) g_pool[i] = 0.f;
        return;
    }
    float sq = 0.f;
    for (int i = t; i < L; i += 32) { float v = src[i]; sq += v*v; }
    #pragma unroll
    for (int off = 16; off; off >>= 1) sq += __shfl_xor_sync(0xffffffffu, sq, off);
    float rn = 1.0f / sqrtf(sq);
    for (int i = t; i < L; i += 32) dst[i] = src[i] * rn;
}

// ---------------- K1: LayerNorm1 + pw1 (64 -> 128), per-pixel matvec ----------
__global__ void __launch_bounds__(128) k1(const float* __restrict__ inp,
                                          const float* __restrict__ b1,
                                          const float* __restrict__ ln1w,
                                          const float* __restrict__ ln1b) {
    __shared__ float Ws[DW*C];
    __shared__ float bs[DW];
    __shared__ float lw[C], lb[C];
    int b = blockIdx.y;
    const float* Wg = g_w1 + (size_t)b*DW*C;
    for (int i = threadIdx.x; i < DW*C; i += 128) Ws[i] = Wg[i];
    if (threadIdx.x < DW) bs[threadIdx.x] = b1[b*DW + threadIdx.x];
    if (threadIdx.x < C)  { lw[threadIdx.x] = ln1w[threadIdx.x]; lb[threadIdx.x] = ln1b[threadIdx.x]; }
    __syncthreads();

    int p = blockIdx.x * 128 + threadIdx.x;
    const float* xin = inp + (size_t)b*C*HW + p;
    float xr[C];
    float sum = 0.f, sq = 0.f;
    #pragma unroll
    for (int c = 0; c < C; c++) { float v = xin[(size_t)c*HW]; xr[c] = v; sum += v; sq += v*v; }
    float mu  = sum * (1.f/C);
    float var = sq  * (1.f/C) - mu*mu;
    float s   = rsqrtf(var + EPS);
    #pragma unroll
    for (int c = 0; c < C; c++) xr[c] = (xr[c] - mu) * s * lw[c] + lb[c];

    float* out = g_t1 + (size_t)b*DW*HW + p;
    #pragma unroll 2
    for (int o = 0; o < DW; o++) {
        float acc = bs[o];
        const float* wrow = &Ws[o*C];
        #pragma unroll
        for (int c = 0; c < C; c++) acc += wrow[c] * xr[c];
        out[(size_t)o*HW] = acc;
    }
}

// ---------------- K_dw: depthwise 3x3 + SimpleGate + pool partials ------------
__global__ void __launch_bounds__(256) kdw(const float* __restrict__ b2) {
    int bc = blockIdx.z; int b = bc >> 6; int c = bc & 63;
    __shared__ float s1[10][34];
    __shared__ float s2[10][34];
    __shared__ float wA[9], wB[9];
    __shared__ float bAB[2];
    __shared__ float red[8];

    const float* in1 = g_t1 + ((size_t)b*DW + c     ) * HW;
    const float* in2 = g_t1 + ((size_t)b*DW + c + 64) * HW;
    int x0 = blockIdx.x * 32, y0 = blockIdx.y * 8;

    for (int i = threadIdx.x; i < 340; i += 256) {
        int ly = i / 34, lx = i % 34;
        int gy = y0 + ly - 1, gx = x0 + lx - 1;
        bool ok = (gy >= 0 && gy < IH && gx >= 0 && gx < IW);
        s1[ly][lx] = ok ? in1[gy*IW + gx] : 0.f;
        s2[ly][lx] = ok ? in2[gy*IW + gx] : 0.f;
    }
    if (threadIdx.x < 9)        wA[threadIdx.x]      = g_w2[((size_t)b*DW + c     )*9 + threadIdx.x];
    else if (threadIdx.x < 18)  wB[threadIdx.x - 9]  = g_w2[((size_t)b*DW + c + 64)*9 + threadIdx.x - 9];
    else if (threadIdx.x == 18) bAB[0] = b2[b*DW + c];
    else if (threadIdx.x == 19) bAB[1] = b2[b*DW + c + 64];
    __syncthreads();

    int lx = threadIdx.x & 31, ly = threadIdx.x >> 5;
    float a = bAB[0], d = bAB[1];
    #pragma unroll
    for (int ky = 0; ky < 3; ky++)
        #pragma unroll
        for (int kx = 0; kx < 3; kx++) {
            a += wA[ky*3 + kx] * s1[ly + ky][lx + kx];
            d += wB[ky*3 + kx] * s2[ly + ky][lx + kx];
        }
    float g = a * d;
    g_t2[((size_t)b*C + c)*HW + (y0 + ly)*IW + (x0 + lx)] = g;

    // reduce for global average pool
    float v = g;
    #pragma unroll
    for (int off = 16; off; off >>= 1) v += __shfl_down_sync(0xffffffffu, v, off);
    if (lx == 0) red[ly] = v;
    __syncthreads();
    if (threadIdx.x == 0) {
        float t = 0.f;
        #pragma unroll
        for (int i = 0; i < 8; i++) t += red[i];
        atomicAdd(&g_pool[b*C + c], t);
    }
}

// ---------------- K_sca: sca = sca_w @ (pool/HW) + sca_b ----------------------
__global__ void ksca(const float* __restrict__ sca_w, const float* __restrict__ sca_b) {
    int b = blockIdx.x, o = threadIdx.x;
    float acc = sca_b[o];
    #pragma unroll 8
    for (int cc = 0; cc < C; cc++)
        acc += sca_w[o*C + cc] * (g_pool[b*C + cc] * (1.f/(float)HW));
    g_sca[b*C + o] = acc;
}

// ---------------- K2: sca*x -> pw3 -> +inp*beta -> LN2 -> pw4 -> gate -> pw5 -> out
__global__ void __launch_bounds__(128) k2(const float* __restrict__ inp,
                                          const float* __restrict__ b3,
                                          const float* __restrict__ b4,
                                          const float* __restrict__ b5,
                                          const float* __restrict__ ln2w,
                                          const float* __restrict__ ln2b,
                                          const float* __restrict__ beta,
                                          const float* __restrict__ gamma,
                                          float* __restrict__ out) {
    __shared__ float Wbuf[DW*C];     // reused for W3 (4096), W4 (8192), W5 (4096)
    __shared__ float b3s[C], b4s[DW], b5s[C];
    __shared__ float l2w[C], l2b[C], il2w[C], bet[C], gam[C], scs[C];
    int b = blockIdx.y;

    if (threadIdx.x < C) {
        int t = threadIdx.x;
        b3s[t] = b3[b*C + t];
        b5s[t] = b5[b*C + t];
        float w = ln2w[t];
        l2w[t] = w; l2b[t] = ln2b[t]; il2w[t] = 1.f / w;
        bet[t] = beta[t]; gam[t] = gamma[t];
        scs[t] = g_sca[b*C + t];
    } else {
        int t = threadIdx.x - C;
        b4s[t]     = b4[b*DW + t];
        b4s[t+64]  = b4[b*DW + t + 64];
    }
    // phase 1 weights: W3
    {
        const float* Wg = g_w3 + (size_t)b*C*C;
        for (int i = threadIdx.x; i < C*C; i += 128) Wbuf[i] = Wg[i];
    }
    __syncthreads();

    int p = blockIdx.x * 128 + threadIdx.x;

    // load gated tensor, apply channel attention
    float x[C];
    const float* t2p = g_t2 + (size_t)b*C*HW + p;
    #pragma unroll
    for (int c = 0; c < C; c++) x[c] = t2p[(size_t)c*HW] * scs[c];

    // pw3 + residual -> y ; LN2 stats on the fly
    float y[C];
    const float* ip = inp + (size_t)b*C*HW + p;
    float sum = 0.f, sq = 0.f;
    #pragma unroll 2
    for (int o = 0; o < C; o++) {
        float acc = b3s[o];
        const float* wrow = &Wbuf[o*C];
        #pragma unroll
        for (int c = 0; c < C; c++) acc += wrow[c] * x[c];
        float yv = ip[(size_t)o*HW] + acc * bet[o];
        y[o] = yv; sum += yv; sq += yv*yv;
    }
    float mu  = sum * (1.f/C);
    float var = sq  * (1.f/C) - mu*mu;
    float s   = rsqrtf(var + EPS);
    float is  = sqrtf(var + EPS);     // to recover raw y later
    #pragma unroll
    for (int o = 0; o < C; o++) y[o] = (y[o] - mu) * s * l2w[o] + l2b[o];  // y now holds yn

    // phase 2 weights: W4 (overwrite buffer)
    __syncthreads();
    {
        const float* Wg = g_w4 + (size_t)b*DW*C;
        for (int i = threadIdx.x; i < DW*C; i += 128) Wbuf[i] = Wg[i];
    }
    __syncthreads();

    // pw4 + SimpleGate -> g (compute paired halves together)
    float gt[C];
    #pragma unroll 1
    for (int c2 = 0; c2 < C; c2++) {
        float a1 = b4s[c2], a2 = b4s[c2 + 64];
        const float* w1r = &Wbuf[c2*C];
        const float* w2r = &Wbuf[(c2 + 64)*C];
        #pragma unroll
        for (int k = 0; k < C; k++) { float yk = y[k]; a1 += w1r[k]*yk; a2 += w2r[k]*yk; }
        gt[c2] = a1 * a2;
    }

    // phase 3 weights: W5
    __syncthreads();
    {
        const float* Wg = g_w5 + (size_t)b*C*C;
        for (int i = threadIdx.x; i < C*C; i += 128) Wbuf[i] = Wg[i];
    }
    __syncthreads();

    // pw5 + recover raw y + final residual
    float* op = out + (size_t)b*C*HW + p;
    #pragma unroll 2
    for (int o = 0; o < C; o++) {
        float acc = b5s[o];
        const float* wrow = &Wbuf[o*C];
        #pragma unroll
        for (int c = 0; c < C; c++) acc += wrow[c] * gt[c];
        float yo = (y[o] - l2b[o]) * il2w[o] * is + mu;   // un-normalize
        op[(size_t)o*HW] = yo + acc * gam[o];
    }
}

// ---------------- launch ------------------------------------------------------
extern "C" void kernel_launch(void* const* d_in, const int* in_sizes, int n_in,
                              void* d_out, int out_size) {
    const float* inp   = (const float*)d_in[0];
    const float* w1    = (const float*)d_in[1];
    const float* b1    = (const float*)d_in[2];
    const float* w2    = (const float*)d_in[3];
    const float* b2    = (const float*)d_in[4];
    const float* w3    = (const float*)d_in[5];
    const float* b3    = (const float*)d_in[6];
    const float* w4    = (const float*)d_in[7];
    const float* b4    = (const float*)d_in[8];
    const float* w5    = (const float*)d_in[9];
    const float* b5    = (const float*)d_in[10];
    const float* ln1w  = (const float*)d_in[11];
    const float* ln1b  = (const float*)d_in[12];
    const float* ln2w  = (const float*)d_in[13];
    const float* ln2b  = (const float*)d_in[14];
    const float* scaw  = (const float*)d_in[15];
    const float* scab  = (const float*)d_in[16];
    const float* beta  = (const float*)d_in[17];
    const float* gamma = (const float*)d_in[18];
    float* out = (float*)d_out;

    k_prep<<<4097, 32>>>(w1, w2, w3, w4, w5);
    k1<<<dim3(HW/128, B), 128>>>(inp, b1, ln1w, ln1b);
    kdw<<<dim3(IW/32, IH/8, B*C), 256>>>(b2);
    ksca<<<B, C>>>(scaw, scab);
    k2<<<dim3(HW/128, B), 128>>>(inp, b3, b4, b5, ln2w, ln2b, beta, gamma, out);
}